// round 1
// baseline (speedup 1.0000x reference)
#include <cuda_runtime.h>
#include <cuda_bf16.h>

#define B_    8
#define TMAX  256
#define UMAX  128
#define V_    512

// Scratch (static device globals: allocation-free per harness rules)
__device__ float g_blank[B_ * TMAX * (UMAX + 1)];   // blank log-prob per (b,t,u)
__device__ float g_emit [B_ * TMAX * UMAX];         // emit  log-prob per (b,t,u<128)
__device__ float g_lp   [B_];                       // per-batch final log-prob

// ---------------------------------------------------------------------------
// Kernel 1: per-(b,t,u) log-softmax reduced to blank/emit log-probs.
// One warp per row of 512 floats. Skips rows outside the active region
// (t >= T_len[b] || u > U_len[b]) -> ~43% less HBM traffic.
// ---------------------------------------------------------------------------
__global__ __launch_bounds__(256) void lse_kernel(const float* __restrict__ logits,
                                                  const int*   __restrict__ y,
                                                  const int*   __restrict__ T_len,
                                                  const int*   __restrict__ U_len)
{
    const int ROWS = B_ * TMAX * (UMAX + 1);
    int row  = blockIdx.x * 8 + (threadIdx.x >> 5);
    int lane = threadIdx.x & 31;
    if (row >= ROWS) return;

    int u  = row % (UMAX + 1);
    int bt = row / (UMAX + 1);
    int t  = bt % TMAX;
    int b  = bt / TMAX;
    if (t >= T_len[b] || u > U_len[b]) return;   // unused by the DP

    const float* rowp = logits + (size_t)row * V_;
    const float4* p   = (const float4*)rowp;

    float4 r0 = p[lane];
    float4 r1 = p[lane + 32];
    float4 r2 = p[lane + 64];
    float4 r3 = p[lane + 96];

    // lane-local max over 16 values
    float m = fmaxf(fmaxf(fmaxf(r0.x, r0.y), fmaxf(r0.z, r0.w)),
                    fmaxf(fmaxf(r1.x, r1.y), fmaxf(r1.z, r1.w)));
    m = fmaxf(m, fmaxf(fmaxf(fmaxf(r2.x, r2.y), fmaxf(r2.z, r2.w)),
                       fmaxf(fmaxf(r3.x, r3.y), fmaxf(r3.z, r3.w))));
    #pragma unroll
    for (int o = 16; o > 0; o >>= 1)
        m = fmaxf(m, __shfl_xor_sync(0xffffffffu, m, o));

    float s = __expf(r0.x - m) + __expf(r0.y - m) + __expf(r0.z - m) + __expf(r0.w - m)
            + __expf(r1.x - m) + __expf(r1.y - m) + __expf(r1.z - m) + __expf(r1.w - m)
            + __expf(r2.x - m) + __expf(r2.y - m) + __expf(r2.z - m) + __expf(r2.w - m)
            + __expf(r3.x - m) + __expf(r3.y - m) + __expf(r3.z - m) + __expf(r3.w - m);
    #pragma unroll
    for (int o = 16; o > 0; o >>= 1)
        s += __shfl_xor_sync(0xffffffffu, s, o);

    float lse = m + __logf(s);

    if (lane == 0) {
        g_blank[row] = r0.x - lse;                           // logits[...,0]
        if (u < UMAX) {
            int yv = y[b * UMAX + u];                        // in [1, V)
            g_emit[(b * TMAX + t) * UMAX + u] = __ldg(rowp + yv) - lse;  // L1/L2 hit
        }
    }
}

// ---------------------------------------------------------------------------
// Kernel 2: alpha DP, anti-diagonal wavefront. One block per batch,
// thread u owns column u. Double-buffered shared row -> 1 barrier/diagonal.
// Depth-4 register prefetch of blank/emit hides L2 latency.
// ---------------------------------------------------------------------------
__global__ __launch_bounds__(160) void dp_kernel(const int* __restrict__ T_len,
                                                 const int* __restrict__ U_len)
{
    const int b = blockIdx.x;
    const int u = threadIdx.x;                 // 0..128 active, rest barrier-only
    const bool th_ok = (u <= UMAX);

    __shared__ float sh[2][UMAX + 2];

    const int T = T_len[b];
    const int U = U_len[b];
    const float* bl = g_blank + b * TMAX * (UMAX + 1);
    const float* em = g_emit  + b * TMAX * UMAX;

    if (threadIdx.x < UMAX + 2) { sh[0][threadIdx.x] = 0.f; sh[1][threadIdx.x] = 0.f; }
    float cur = 0.f;                           // thread 0: alpha[0][0] = 0
    if (u == 0) sh[0][1] = 0.f;
    __syncthreads();

    const int dmax = (T - 1) + U;
    int buf = 0;

    constexpr int PD = 4;                      // prefetch distance (diagonals)
    float blr[PD], emr[PD];
    #pragma unroll
    for (int k = 0; k < PD; ++k) {
        int dd = 1 + k;
        int t  = dd - u;
        int tb = min(max(t - 1, 0), TMAX - 1);
        int te = min(max(t,     0), TMAX - 1);
        int ue = min(max(u - 1, 0), UMAX - 1);
        blr[k] = th_ok ? __ldg(bl + tb * (UMAX + 1) + u) : 0.f;
        emr[k] = th_ok ? __ldg(em + te * UMAX + ue)      : 0.f;
    }

    #pragma unroll 4
    for (int d = 1; d <= dmax; ++d) {
        const int slot = (d - 1) & (PD - 1);
        const float blv = blr[slot];
        const float emv = emr[slot];

        // prefetch for diagonal d + PD (addresses clamped; unused when inactive)
        {
            int dd = d + PD;
            int t  = dd - u;
            int tb = min(max(t - 1, 0), TMAX - 1);
            int te = min(max(t,     0), TMAX - 1);
            int ue = min(max(u - 1, 0), UMAX - 1);
            if (th_ok) {
                blr[slot] = __ldg(bl + tb * (UMAX + 1) + u);
                emr[slot] = __ldg(em + te * UMAX + ue);
            }
        }

        const int  t      = d - u;
        const bool active = th_ok && (u <= U) && (t >= 0) && (t < T);
        float left = 0.f;
        if (th_ok) left = sh[buf][u];          // alpha[t][u-1] from thread u-1

        if (active) {
            if (t == 0) {                      // first row: cumsum of emit
                cur = left + emv;
            } else if (u == 0) {               // first col: blank chain
                cur = cur + blv;
            } else {                           // logaddexp(alpha[t-1][u]+blank, alpha[t][u-1]+emit)
                float x  = cur  + blv;
                float yv = left + emv;
                float mx = fmaxf(x, yv);
                cur = mx + __logf(__expf(x - mx) + __expf(yv - mx));
            }
            sh[buf ^ 1][u + 1] = cur;
        }
        __syncthreads();
        buf ^= 1;
    }

    // thread u == U stopped updating at t = T-1, so cur == alpha[T-1][U]
    if (th_ok && u == U)
        g_lp[b] = cur + __ldg(bl + (T - 1) * (UMAX + 1) + U);
}

// ---------------------------------------------------------------------------
// Kernel 3: loss = -mean(log_probs)
// ---------------------------------------------------------------------------
__global__ void finalize_kernel(float* __restrict__ out)
{
    float s = (threadIdx.x < B_) ? g_lp[threadIdx.x] : 0.f;
    #pragma unroll
    for (int o = 4; o > 0; o >>= 1)
        s += __shfl_xor_sync(0xffffffffu, s, o);
    if (threadIdx.x == 0) out[0] = -s / (float)B_;
}

extern "C" void kernel_launch(void* const* d_in, const int* in_sizes, int n_in,
                              void* d_out, int out_size)
{
    const float* logits = (const float*)d_in[0];
    const int*   y      = (const int*)  d_in[1];
    const int*   T_len  = (const int*)  d_in[2];
    const int*   U_len  = (const int*)  d_in[3];
    float*       out    = (float*)d_out;

    const int ROWS = B_ * TMAX * (UMAX + 1);       // 264192 warps
    lse_kernel<<<(ROWS + 7) / 8, 256>>>(logits, y, T_len, U_len);
    dp_kernel<<<B_, 160>>>(T_len, U_len);
    finalize_kernel<<<1, 32>>>(out);
}

// round 2
// speedup vs baseline: 2.3381x; 2.3381x over previous
#include <cuda_runtime.h>
#include <cuda_bf16.h>

#define B_    8
#define TMAX  256
#define UMAX  128
#define V_    512

#define LOG2E 1.4426950408889634f
#define LN2   0.6931471805599453f
#define NEGF  (-1e30f)

// Guarded scratch: dp threads issue prefetch loads up to ~132 diagonals past the
// valid region in both directions; guards make those loads safe (values unused).
#define GB 17024
#define GA 18432
__device__ float g_blank_pad[GB + B_ * TMAX * (UMAX + 1) + GA]; // log2-domain blank lp
__device__ float g_emit_pad [GB + B_ * TMAX * UMAX       + GA]; // log2-domain emit lp
__device__ float g_lp[B_];                                      // per-batch final (log2-domain)

__device__ __forceinline__ float ex2f(float x) { float r; asm("ex2.approx.ftz.f32 %0,%1;" : "=f"(r) : "f"(x)); return r; }
__device__ __forceinline__ float lg2f(float x) { float r; asm("lg2.approx.ftz.f32 %0,%1;" : "=f"(r) : "f"(x)); return r; }

// ---------------------------------------------------------------------------
// Kernel 1: per-(b,t,u) log-softmax reduced to blank/emit log-probs (log2 dom).
// One warp per 512-float row; rows outside the active region are skipped.
// ---------------------------------------------------------------------------
__global__ __launch_bounds__(256) void lse_kernel(const float* __restrict__ logits,
                                                  const int*   __restrict__ y,
                                                  const int*   __restrict__ T_len,
                                                  const int*   __restrict__ U_len)
{
    const int ROWS = B_ * TMAX * (UMAX + 1);
    int row  = blockIdx.x * 8 + (threadIdx.x >> 5);
    int lane = threadIdx.x & 31;
    if (row >= ROWS) return;

    int u  = row % (UMAX + 1);
    int bt = row / (UMAX + 1);
    int t  = bt % TMAX;
    int b  = bt / TMAX;
    if (t >= T_len[b] || u > U_len[b]) return;   // never consumed by the DP

    const float* rowp = logits + (size_t)row * V_;
    const float4* p   = (const float4*)rowp;

    float4 r0 = p[lane];
    float4 r1 = p[lane + 32];
    float4 r2 = p[lane + 64];
    float4 r3 = p[lane + 96];

    float m = fmaxf(fmaxf(fmaxf(r0.x, r0.y), fmaxf(r0.z, r0.w)),
                    fmaxf(fmaxf(r1.x, r1.y), fmaxf(r1.z, r1.w)));
    m = fmaxf(m, fmaxf(fmaxf(fmaxf(r2.x, r2.y), fmaxf(r2.z, r2.w)),
                       fmaxf(fmaxf(r3.x, r3.y), fmaxf(r3.z, r3.w))));
    #pragma unroll
    for (int o = 16; o > 0; o >>= 1)
        m = fmaxf(m, __shfl_xor_sync(0xffffffffu, m, o));

    float s = __expf(r0.x - m) + __expf(r0.y - m) + __expf(r0.z - m) + __expf(r0.w - m)
            + __expf(r1.x - m) + __expf(r1.y - m) + __expf(r1.z - m) + __expf(r1.w - m)
            + __expf(r2.x - m) + __expf(r2.y - m) + __expf(r2.z - m) + __expf(r2.w - m)
            + __expf(r3.x - m) + __expf(r3.y - m) + __expf(r3.z - m) + __expf(r3.w - m);
    #pragma unroll
    for (int o = 16; o > 0; o >>= 1)
        s += __shfl_xor_sync(0xffffffffu, s, o);

    float lse = m + __logf(s);

    if (lane == 0) {
        g_blank_pad[GB + row] = (r0.x - lse) * LOG2E;
        if (u < UMAX) {
            int yv = y[b * UMAX + u];
            g_emit_pad[GB + (b * TMAX + t) * UMAX + u] = (__ldg(rowp + yv) - lse) * LOG2E;
        }
    }
}

// ---------------------------------------------------------------------------
// Kernel 2: alpha DP, anti-diagonal wavefront in log2 domain.
// One block per batch; thread u owns column u. Branch-free cell update,
// pointer-incremented depth-4 prefetch in named registers, 4x unrolled loop
// with trip count rounded up (extra diagonals are uniform no-ops).
// ---------------------------------------------------------------------------
__global__ __launch_bounds__(160) void dp_kernel(const int* __restrict__ T_len,
                                                 const int* __restrict__ U_len)
{
    const int  b     = blockIdx.x;
    const int  u     = threadIdx.x;             // 0..128 active
    const bool th_ok = (u <= UMAX);
    const bool u0    = (u == 0);

    __shared__ float sh[2][192];

    const int T = T_len[b];
    const int U = U_len[b];
    const float* blb = g_blank_pad + GB + b * TMAX * (UMAX + 1);
    const float* emb = g_emit_pad  + GB + b * TMAX * UMAX;

    if (threadIdx.x < 192) { sh[0][threadIdx.x] = 0.f; sh[1][threadIdx.x] = 0.f; }
    float cur = 0.f;                            // alpha[0][0] = 0 (thread 0)
    __syncthreads();

    // operand pointers for diagonal dd: blank (dd-u-1)*129 + u, emit (dd-u)*128 + (u-1)
    const float* pb = blb + (-u) * (UMAX + 1) + u;       // dd = 1
    const float* pe = emb + (1 - u) * UMAX + (u - 1);

    float b0 = 0.f, b1 = 0.f, b2 = 0.f, b3 = 0.f;
    float e0 = 0.f, e1 = 0.f, e2 = 0.f, e3 = 0.f;
    if (th_ok) {
        b0 = __ldg(pb); e0 = __ldg(pe); pb += UMAX + 1; pe += UMAX;
        b1 = __ldg(pb); e1 = __ldg(pe); pb += UMAX + 1; pe += UMAX;
        b2 = __ldg(pb); e2 = __ldg(pe); pb += UMAX + 1; pe += UMAX;
        b3 = __ldg(pb); e3 = __ldg(pe); pb += UMAX + 1; pe += UMAX;
    } else {
        pb += 4 * (UMAX + 1); pe += 4 * UMAX;
    }

    const int dmax  = (T - 1) + U;
    const int dmaxR = ((dmax + 3) >> 2) << 2;   // uniform across the block
    int buf = 0;

#define DP_STEP(BR, ER, DI)                                              \
    {                                                                    \
        const float blv = BR, emv = ER;                                  \
        if (th_ok) { BR = __ldg(pb); ER = __ldg(pe); }                   \
        pb += UMAX + 1; pe += UMAX;                                      \
        const float left = sh[buf][u];                                   \
        const float x  = ((DI) == u) ? NEGF : cur + blv;                 \
        const float yv = u0          ? NEGF : left + emv;                \
        const float mx = fmaxf(x, yv);                                   \
        const float nc = mx + lg2f(ex2f(x - mx) + ex2f(yv - mx));        \
        const int   t  = (DI) - u;                                       \
        const bool act = th_ok && (u <= U) && (t >= 0) && (t < T);       \
        cur = act ? nc : cur;                                            \
        if (act) sh[buf ^ 1][u + 1] = cur;                               \
        __syncthreads();                                                 \
        buf ^= 1;                                                        \
    }

    for (int d = 1; d <= dmaxR; d += 4) {
        DP_STEP(b0, e0, d)
        DP_STEP(b1, e1, d + 1)
        DP_STEP(b2, e2, d + 2)
        DP_STEP(b3, e3, d + 3)
    }
#undef DP_STEP

    // thread u == U last updated at t = T-1 -> cur = alpha[T-1][U] (log2 domain)
    if (th_ok && u == U)
        g_lp[b] = cur + __ldg(blb + (T - 1) * (UMAX + 1) + U);
}

// ---------------------------------------------------------------------------
// Kernel 3: loss = -mean(log_probs), converting log2 -> natural log.
// ---------------------------------------------------------------------------
__global__ void finalize_kernel(float* __restrict__ out)
{
    float s = (threadIdx.x < B_) ? g_lp[threadIdx.x] : 0.f;
    #pragma unroll
    for (int o = 4; o > 0; o >>= 1)
        s += __shfl_xor_sync(0xffffffffu, s, o);
    if (threadIdx.x == 0) out[0] = -(s * LN2) / (float)B_;
}

extern "C" void kernel_launch(void* const* d_in, const int* in_sizes, int n_in,
                              void* d_out, int out_size)
{
    const float* logits = (const float*)d_in[0];
    const int*   y      = (const int*)  d_in[1];
    const int*   T_len  = (const int*)  d_in[2];
    const int*   U_len  = (const int*)  d_in[3];
    float*       out    = (float*)d_out;

    const int ROWS = B_ * TMAX * (UMAX + 1);
    lse_kernel<<<(ROWS + 7) / 8, 256>>>(logits, y, T_len, U_len);
    dp_kernel<<<B_, 160>>>(T_len, U_len);
    finalize_kernel<<<1, 32>>>(out);
}